// round 14
// baseline (speedup 1.0000x reference)
#include <cuda_runtime.h>

#define NTAG  9
#define SEQ   512
#define BATCH 4096
#define CL    32                  // chunk length
#define WARM  8                   // warmup steps (direction error ~0.1^8)
#define NCHUNK (SEQ / CL)         // 16
#define NPART  (32 * NCHUNK)      // 512 partial slots
#define STAGES 3
#define STAGEF (9 * 128 * 4)      // floats per stage (9 pieces x 128 threads x 4)
#define DSMEM  (STAGES * STAGEF * 4)   // 55296 bytes

// ---- device scratch (globals: allocation-free) ----
__device__ int    g_len[BATCH];
__device__ int    g_hist[SEQ + 1];      // zero-init BSS; re-zeroed by prefix kernel
__device__ int    g_binoff[SEQ + 1];
__device__ int    g_perm[BATCH];
__device__ double g_pacc[NPART];

// ============ 1) lengths + histogram (warp per sequence) ============
__global__ void __launch_bounds__(128) crf_len_hist(const int* __restrict__ mask)
{
    const int lane = threadIdx.x & 31;
    const int seq  = blockIdx.x * 4 + (threadIdx.x >> 5);
    const int4* m4 = reinterpret_cast<const int4*>(mask + (size_t)seq * SEQ);
    int s = 0;
#pragma unroll
    for (int k = 0; k < 4; k++) {
        int4 v = m4[lane + 32 * k];
        s += v.x + v.y + v.z + v.w;
    }
#pragma unroll
    for (int o = 16; o; o >>= 1) s += __shfl_xor_sync(0xffffffffu, s, o);
    if (lane == 0) {
        g_len[seq] = s;
        atomicAdd(&g_hist[s], 1);
    }
}

// ============ 2) exclusive prefix over hist -> binoff; re-zero hist ============
__global__ void __launch_bounds__(512) crf_prefix()
{
    __shared__ int a[512], b[512];
    const int tid = threadIdx.x;
    a[tid] = g_hist[tid];
    __syncthreads();
    int* src = a; int* dst = b;
#pragma unroll
    for (int off = 1; off < 512; off <<= 1) {
        dst[tid] = (tid >= off) ? src[tid] + src[tid - off] : src[tid];
        __syncthreads();
        int* t = src; src = dst; dst = t;
    }
    g_binoff[tid + 1] = src[tid];
    if (tid == 0) g_binoff[0] = 0;
    g_hist[tid] = 0;
    if (tid == 0) g_hist[512] = 0;
}

// ============ 3) scatter: counting-sort permutation by length ============
__global__ void __launch_bounds__(128) crf_scatter()
{
    const int bseq = blockIdx.x * 128 + threadIdx.x;
    const int L    = g_len[bseq];
    const int slot = atomicAdd(&g_binoff[L], 1);
    g_perm[slot] = bseq;
}

// ============ 4) chunked scan, one (sequence, chunk) per LANE.
//  Stage layout is PIECE-MAJOR: piece q of thread p lives at bytes
//  q*2048 + p*16  ->  every cp.async dst is 16B-aligned and the read-back
//  LDS.128 at (tid*16 + q*2048) is perfectly coalesced (conflict-free).
//  Quad register indexing: element (row r, tag j) = bq[9*r + j]  (gmem order).
__global__ void __launch_bounds__(128, 3) crf_scan(
    const float* __restrict__ bert,  // [B, S, 9] f32
    const int* __restrict__ tags,    // [B, S] i32
    const float* __restrict__ trans) // [11, 11] f32
{
    extern __shared__ float dsm[];   // [STAGES][9][128][4] floats
    __shared__ float  sT[121];
    __shared__ int    sBase[128];
    __shared__ int    sMax[4];
    __shared__ double sAcc;

    const int tid = threadIdx.x;
    if (tid < 121) sT[tid] = trans[tid];
    if (tid == 0) sAcc = 0.0;

    const int c    = blockIdx.y;               // chunk id (CTA-uniform)
    const int slot = blockIdx.x * 128 + tid;   // sorted slot
    const int seq  = g_perm[slot];
    const int L    = g_len[seq];
    const int s    = c * CL;
    const bool act = (s < L);
    const int t0s  = (c == 0) ? 0 : s - WARM;  // CTA-uniform, divisible by 4
    const int tB   = act ? min(s + CL, L) : 0;

    sBase[tid] = seq * (SEQ * NTAG);
    __syncthreads();

    // CTA max of tB -> uniform quad count
    {
        int m = tB;
#pragma unroll
        for (int o = 16; o; o >>= 1) m = max(m, __shfl_xor_sync(0xffffffffu, m, o));
        if ((tid & 31) == 0) sMax[tid >> 5] = m;
    }
    __syncthreads();
    const int maxtB = max(max(sMax[0], sMax[1]), max(sMax[2], sMax[3]));
    const int nq = (maxtB > t0s) ? ((maxtB - t0s + 3) >> 2) : 0;

    // E = exp(T[:9,:9]) register-resident
    float E[NTAG][NTAG];
#pragma unroll
    for (int i = 0; i < NTAG; i++)
#pragma unroll
        for (int j = 0; j < NTAG; j++)
            E[i][j] = __expf(sT[i * 11 + j]);

    // piece constants: piece f = tid + 128k covers seq p = f/9, 16B chunk q = f%9
    int goff[9], doffB[9];
#pragma unroll
    for (int k = 0; k < 9; k++) {
        const int f = tid + 128 * k;
        const int p = f / 9;
        const int q = f - 9 * p;
        goff[k]  = sBase[p] + q * 4;            // float offset into bert (+ t0*9)
        doffB[k] = q * 2048 + p * 16;           // byte offset into stage (16B aligned)
    }

    const unsigned sm0 = (unsigned)__cvta_generic_to_shared(dsm);
    auto issue = [&](int q) {
        const int t0f = min(t0s + 4 * q, SEQ - 4) * 9;   // clamped, always valid
        const unsigned sb = sm0 + (unsigned)((q % STAGES) * STAGEF) * 4u;
#pragma unroll
        for (int k = 0; k < 9; k++) {
            const float* src = bert + goff[k] + t0f;
            asm volatile("cp.async.ca.shared.global [%0], [%1], 16;"
                         :: "r"(sb + (unsigned)doffB[k]), "l"(src));
        }
        asm volatile("cp.async.commit_group;");
    };

    const int* tg = tags + (size_t)seq * SEQ;

    float W[NTAG];
    int   eAcc = 0, eRef = 0, prev = 0;
    float SRef = 0.0f, rg = 0.0f;
    const int gs = (c == 0) ? 1 : s;
    if (act && c > 0) {
#pragma unroll
        for (int j = 0; j < NTAG; j++) W[j] = 1.0f;
        prev = __ldg(tg + s - 1);
    }

    if (nq > 0) {
        issue(0);
        issue(1);
        int4 tq = __ldg(reinterpret_cast<const int4*>(tg + t0s));

        for (int q = 0; q < nq; ++q) {
            asm volatile("cp.async.wait_group 1;");
            __syncthreads();

            // own quad: 9x LDS.128, coalesced & conflict-free.
            // bq[i] = em[(t0)*9 + i] -> element (row r, tag j) = bq[9r + j]
            float bq[36];
            const float* stg = dsm + (q % STAGES) * STAGEF;
#pragma unroll
            for (int k = 0; k < 9; k++) {
                const float4 v = *reinterpret_cast<const float4*>(stg + k * 512 + tid * 4);
                bq[4 * k + 0] = v.x; bq[4 * k + 1] = v.y;
                bq[4 * k + 2] = v.z; bq[4 * k + 3] = v.w;
            }
            const int tags4[4] = {tq.x, tq.y, tq.z, tq.w};
            if (q + 1 < nq)
                tq = __ldg(reinterpret_cast<const int4*>(tg + t0s + 4 * (q + 1)));

            issue(q + 2);   // stage (q+2)%3 == (q-1)%3: consumed before sync above

            const int t0 = t0s + 4 * q;
#pragma unroll
            for (int r = 0; r < 4; r++) {
                const int t = t0 + r;
                if (t < tB) {
                    if (t == 0) {
                        // exact init (c == 0 only); row 0 = bq[0..8]
#pragma unroll
                        for (int j = 0; j < NTAG; j++)
                            W[j] = __expf(sT[99 + j] + bq[j]);
                        prev = tags4[0];
                        float ev = bq[0];
#pragma unroll
                        for (int j = 1; j < NTAG; j++)
                            if (prev == j) ev = bq[j];
                        rg = sT[99 + prev] + ev;
                    } else {
                        // alpha update: W'_j = (sum_i W_i E_ij) * exp(em_tj)
                        float nw[NTAG];
#pragma unroll
                        for (int j = 0; j < NTAG; j++) {
                            float a = W[0] * E[0][j];
#pragma unroll
                            for (int i = 1; i < NTAG; i++) a = fmaf(W[i], E[i][j], a);
                            nw[j] = a * __expf(bq[9 * r + j]);
                        }
                        // exact power-of-2 rescale at t % 4 == 0
                        if (r == 0) {
                            float mx = nw[0];
#pragma unroll
                            for (int j = 1; j < NTAG; j++) mx = fmaxf(mx, nw[j]);
                            const int e = ((__float_as_int(mx) >> 23) & 255) - 127;
                            eAcc += e;
                            const float sc = __int_as_float((127 - e) << 23);
#pragma unroll
                            for (int j = 0; j < NTAG; j++) nw[j] *= sc;
                        }
#pragma unroll
                        for (int j = 0; j < NTAG; j++) W[j] = nw[j];

                        // reference point at end of warmup (c >= 1 only)
                        if (t == s - 1) {
                            eRef = eAcc;
                            float ss = W[0];
#pragma unroll
                            for (int j = 1; j < NTAG; j++) ss += W[j];
                            SRef = __logf(ss);
                        }
                        // gold path inside the window; emit from quad registers
                        if (t >= gs) {
                            const int tag = tags4[r];
                            float ev = bq[9 * r];
#pragma unroll
                            for (int j = 1; j < NTAG; j++)
                                if (tag == j) ev = bq[9 * r + j];
                            rg += sT[prev * 11 + tag] + ev;
                            prev = tag;
                        }
                    }
                }
            }
        }
    }

    double contrib = 0.0;
    if (act) {
        const bool last = (L <= s + CL);       // chunk reaches t = L-1
        float r;
        if (last) {
            float fin = 0.0f;
#pragma unroll
            for (int j = 0; j < NTAG; j++)
                fin = fmaf(W[j], __expf(sT[j * 11 + 10]), fin);
            r  = 0.6931472f * (float)(eAcc - eRef) + __logf(fin) - SRef;
            rg += sT[prev * 11 + 10];
        } else {
            float ss = W[0];
#pragma unroll
            for (int j = 1; j < NTAG; j++) ss += W[j];
            r = 0.6931472f * (float)(eAcc - eRef) + __logf(ss) - SRef;
        }
        contrib = (double)r - (double)rg;
    }

    // warp reduce -> smem -> one global slot per CTA
#pragma unroll
    for (int o = 16; o; o >>= 1)
        contrib += __shfl_down_sync(0xffffffffu, contrib, o);
    if ((tid & 31) == 0) atomicAdd(&sAcc, contrib);
    __syncthreads();
    if (tid == 0) g_pacc[blockIdx.y * 32 + blockIdx.x] = sAcc;
}

// ============ 5) final reduction: partials + num_chars from g_len ============
__global__ void __launch_bounds__(128) crf_fin(float* out)
{
    __shared__ double    sa[128];
    __shared__ long long sc[128];
    const int tid = threadIdx.x;
    double a = 0.0;
    long long ch = 0;
    for (int i = tid; i < NPART; i += 128) a += g_pacc[i];
    for (int i = tid; i < BATCH; i += 128) ch += (long long)g_len[i];
    sa[tid] = a; sc[tid] = ch;
    __syncthreads();
    for (int o = 64; o; o >>= 1) {
        if (tid < o) { sa[tid] += sa[tid + o]; sc[tid] += sc[tid + o]; }
        __syncthreads();
    }
    if (tid == 0) out[0] = (float)(sa[0] / (double)sc[0]);
}

extern "C" void kernel_launch(void* const* d_in, const int* in_sizes, int n_in,
                              void* d_out, int out_size)
{
    const float* bert  = (const float*)d_in[0];
    const int*   mask  = (const int*)d_in[1];
    const int*   tags  = (const int*)d_in[2];
    const float* trans = (const float*)d_in[3];
    float* out = (float*)d_out;

    cudaFuncSetAttribute(crf_scan, cudaFuncAttributeMaxDynamicSharedMemorySize, DSMEM);

    crf_len_hist<<<BATCH / 4, 128>>>(mask);
    crf_prefix<<<1, 512>>>();
    crf_scatter<<<BATCH / 128, 128>>>();
    dim3 grid(32, NCHUNK);
    crf_scan<<<grid, 128, DSMEM>>>(bert, tags, trans);
    crf_fin<<<1, 128>>>(out);
}

// round 15
// speedup vs baseline: 1.3600x; 1.3600x over previous
#include <cuda_runtime.h>

#define NTAG  9
#define SEQ   512
#define BATCH 4096
#define CL    32                  // chunk length
#define WARM  4                   // warmup steps (direction error ~0.1^4 ~ 1e-4)
#define NCHUNK (SEQ / CL)         // 16
#define NPART  (32 * NCHUNK)      // 512 partial slots
#define STAGES 3
#define STAGEF (128 * 36)         // floats per stage (thread-major, 144B/thread)
#define DSMEM  (STAGES * STAGEF * 4)   // 55296 bytes

// ---- device scratch (globals: allocation-free) ----
__device__ int    g_len[BATCH];
__device__ int    g_hist[SEQ + 1];      // zero-init BSS; re-zeroed by prefix kernel
__device__ int    g_binoff[SEQ + 1];
__device__ int    g_perm[BATCH];
__device__ double g_pacc[NPART];

// ============ 1) lengths + histogram (warp per sequence) ============
__global__ void __launch_bounds__(128) crf_len_hist(const int* __restrict__ mask)
{
    const int lane = threadIdx.x & 31;
    const int seq  = blockIdx.x * 4 + (threadIdx.x >> 5);
    const int4* m4 = reinterpret_cast<const int4*>(mask + (size_t)seq * SEQ);
    int s = 0;
#pragma unroll
    for (int k = 0; k < 4; k++) {
        int4 v = m4[lane + 32 * k];
        s += v.x + v.y + v.z + v.w;
    }
#pragma unroll
    for (int o = 16; o; o >>= 1) s += __shfl_xor_sync(0xffffffffu, s, o);
    if (lane == 0) {
        g_len[seq] = s;
        atomicAdd(&g_hist[s], 1);
    }
}

// ============ 2) exclusive prefix over hist -> binoff; re-zero hist ============
__global__ void __launch_bounds__(512) crf_prefix()
{
    __shared__ int a[512], b[512];
    const int tid = threadIdx.x;
    a[tid] = g_hist[tid];
    __syncthreads();
    int* src = a; int* dst = b;
#pragma unroll
    for (int off = 1; off < 512; off <<= 1) {
        dst[tid] = (tid >= off) ? src[tid] + src[tid - off] : src[tid];
        __syncthreads();
        int* t = src; src = dst; dst = t;
    }
    g_binoff[tid + 1] = src[tid];
    if (tid == 0) g_binoff[0] = 0;
    g_hist[tid] = 0;
    if (tid == 0) g_hist[512] = 0;
}

// ============ 3) scatter: counting-sort permutation by length ============
__global__ void __launch_bounds__(128) crf_scatter()
{
    const int bseq = blockIdx.x * 128 + threadIdx.x;
    const int L    = g_len[bseq];
    const int slot = atomicAdd(&g_binoff[L], 1);
    g_perm[slot] = bseq;
}

// ============ 4) chunked scan, one (sequence, chunk) per LANE.
//  Stage layout THREAD-MAJOR: piece q of thread p at bytes p*144 + q*16.
//    - cp.async dst 16B-aligned (144 = 9*16), and consecutive pieces are
//      +16B -> smem WRITE banks spread (no conflicts).
//    - read-back: thread tid reads its 36 floats at tid*144 via 9x LDS.128;
//      8-lane phases have word-stride 36 == bank-stride 4 -> conflict-free.
//  Quad register indexing: element (row r, tag j) = bq[9*r + j] (gmem order).
__global__ void __launch_bounds__(128, 3) crf_scan(
    const float* __restrict__ bert,  // [B, S, 9] f32
    const int* __restrict__ tags,    // [B, S] i32
    const float* __restrict__ trans) // [11, 11] f32
{
    extern __shared__ float dsm[];   // [STAGES][128][36] floats
    __shared__ float  sT[121];
    __shared__ int    sBase[128];
    __shared__ int    sMax[4];
    __shared__ double sAcc;

    const int tid = threadIdx.x;
    if (tid < 121) sT[tid] = trans[tid];
    if (tid == 0) sAcc = 0.0;

    const int c    = blockIdx.y;               // chunk id (CTA-uniform)
    const int slot = blockIdx.x * 128 + tid;   // sorted slot
    const int seq  = g_perm[slot];
    const int L    = g_len[seq];
    const int s    = c * CL;
    const bool act = (s < L);
    const int t0s  = (c == 0) ? 0 : s - WARM;  // CTA-uniform, divisible by 4
    const int tB   = act ? min(s + CL, L) : 0;

    sBase[tid] = seq * (SEQ * NTAG);
    __syncthreads();

    // CTA max of tB -> uniform quad count
    {
        int m = tB;
#pragma unroll
        for (int o = 16; o; o >>= 1) m = max(m, __shfl_xor_sync(0xffffffffu, m, o));
        if ((tid & 31) == 0) sMax[tid >> 5] = m;
    }
    __syncthreads();
    const int maxtB = max(max(sMax[0], sMax[1]), max(sMax[2], sMax[3]));
    const int nq = (maxtB > t0s) ? ((maxtB - t0s + 3) >> 2) : 0;

    // E = exp(T[:9,:9]) register-resident
    float E[NTAG][NTAG];
#pragma unroll
    for (int i = 0; i < NTAG; i++)
#pragma unroll
        for (int j = 0; j < NTAG; j++)
            E[i][j] = __expf(sT[i * 11 + j]);

    // piece constants: piece f = tid + 128k covers seq p = f/9, 16B chunk q = f%9
    int goff[9], doffB[9];
#pragma unroll
    for (int k = 0; k < 9; k++) {
        const int f = tid + 128 * k;
        const int p = f / 9;
        const int q = f - 9 * p;
        goff[k]  = sBase[p] + q * 4;            // float offset into bert (+ t0*9)
        doffB[k] = p * 144 + q * 16;            // byte offset into stage (16B aligned)
    }

    const unsigned sm0 = (unsigned)__cvta_generic_to_shared(dsm);
    auto issue = [&](int q) {
        const int t0f = min(t0s + 4 * q, SEQ - 4) * 9;   // clamped, always valid
        const unsigned sb = sm0 + (unsigned)((q % STAGES) * STAGEF) * 4u;
#pragma unroll
        for (int k = 0; k < 9; k++) {
            const float* src = bert + goff[k] + t0f;
            asm volatile("cp.async.ca.shared.global [%0], [%1], 16;"
                         :: "r"(sb + (unsigned)doffB[k]), "l"(src));
        }
        asm volatile("cp.async.commit_group;");
    };

    const int* tg = tags + (size_t)seq * SEQ;

    float W[NTAG];
    int   eAcc = 0, eRef = 0, prev = 0;
    float SRef = 0.0f, rg = 0.0f;
    const int gs = (c == 0) ? 1 : s;
    if (act && c > 0) {
#pragma unroll
        for (int j = 0; j < NTAG; j++) W[j] = 1.0f;
        prev = __ldg(tg + s - 1);
    }

    if (nq > 0) {
        issue(0);
        issue(1);
        int4 tq = __ldg(reinterpret_cast<const int4*>(tg + t0s));

        for (int q = 0; q < nq; ++q) {
            asm volatile("cp.async.wait_group 1;");
            __syncthreads();

            // own quad: 9x LDS.128 at tid*144, conflict-free.
            // bq[m] = em[t0*9 + m] -> element (row r, tag j) = bq[9r + j]
            float bq[36];
            const float* myq = dsm + (q % STAGES) * STAGEF + tid * 36;
#pragma unroll
            for (int k = 0; k < 9; k++) {
                const float4 v = *reinterpret_cast<const float4*>(myq + 4 * k);
                bq[4 * k + 0] = v.x; bq[4 * k + 1] = v.y;
                bq[4 * k + 2] = v.z; bq[4 * k + 3] = v.w;
            }
            const int tags4[4] = {tq.x, tq.y, tq.z, tq.w};
            if (q + 1 < nq)
                tq = __ldg(reinterpret_cast<const int4*>(tg + t0s + 4 * (q + 1)));

            issue(q + 2);   // stage (q+2)%3 == (q-1)%3: consumed before sync above

            const int t0 = t0s + 4 * q;
#pragma unroll
            for (int r = 0; r < 4; r++) {
                const int t = t0 + r;
                if (t < tB) {
                    if (t == 0) {
                        // exact init (c == 0 only); row 0 = bq[0..8]
#pragma unroll
                        for (int j = 0; j < NTAG; j++)
                            W[j] = __expf(sT[99 + j] + bq[j]);
                        prev = tags4[0];
                        float ev = bq[0];
#pragma unroll
                        for (int j = 1; j < NTAG; j++)
                            if (prev == j) ev = bq[j];
                        rg = sT[99 + prev] + ev;
                    } else {
                        // alpha update: W'_j = (sum_i W_i E_ij) * exp(em_tj)
                        float nw[NTAG];
#pragma unroll
                        for (int j = 0; j < NTAG; j++) {
                            float a = W[0] * E[0][j];
#pragma unroll
                            for (int i = 1; i < NTAG; i++) a = fmaf(W[i], E[i][j], a);
                            nw[j] = a * __expf(bq[9 * r + j]);
                        }
                        // exact power-of-2 rescale at t % 4 == 0
                        if (r == 0) {
                            float mx = nw[0];
#pragma unroll
                            for (int j = 1; j < NTAG; j++) mx = fmaxf(mx, nw[j]);
                            const int e = ((__float_as_int(mx) >> 23) & 255) - 127;
                            eAcc += e;
                            const float sc = __int_as_float((127 - e) << 23);
#pragma unroll
                            for (int j = 0; j < NTAG; j++) nw[j] *= sc;
                        }
#pragma unroll
                        for (int j = 0; j < NTAG; j++) W[j] = nw[j];

                        // reference point at end of warmup (c >= 1 only)
                        if (t == s - 1) {
                            eRef = eAcc;
                            float ss = W[0];
#pragma unroll
                            for (int j = 1; j < NTAG; j++) ss += W[j];
                            SRef = __logf(ss);
                        }
                        // gold path inside the window; emit from quad registers
                        if (t >= gs) {
                            const int tag = tags4[r];
                            float ev = bq[9 * r];
#pragma unroll
                            for (int j = 1; j < NTAG; j++)
                                if (tag == j) ev = bq[9 * r + j];
                            rg += sT[prev * 11 + tag] + ev;
                            prev = tag;
                        }
                    }
                }
            }
        }
    }

    double contrib = 0.0;
    if (act) {
        const bool last = (L <= s + CL);       // chunk reaches t = L-1
        float r;
        if (last) {
            float fin = 0.0f;
#pragma unroll
            for (int j = 0; j < NTAG; j++)
                fin = fmaf(W[j], __expf(sT[j * 11 + 10]), fin);
            r  = 0.6931472f * (float)(eAcc - eRef) + __logf(fin) - SRef;
            rg += sT[prev * 11 + 10];
        } else {
            float ss = W[0];
#pragma unroll
            for (int j = 1; j < NTAG; j++) ss += W[j];
            r = 0.6931472f * (float)(eAcc - eRef) + __logf(ss) - SRef;
        }
        contrib = (double)r - (double)rg;
    }

    // warp reduce -> smem -> one global slot per CTA
#pragma unroll
    for (int o = 16; o; o >>= 1)
        contrib += __shfl_down_sync(0xffffffffu, contrib, o);
    if ((tid & 31) == 0) atomicAdd(&sAcc, contrib);
    __syncthreads();
    if (tid == 0) g_pacc[blockIdx.y * 32 + blockIdx.x] = sAcc;
}

// ============ 5) final reduction: partials + num_chars from g_len ============
__global__ void __launch_bounds__(128) crf_fin(float* out)
{
    __shared__ double    sa[128];
    __shared__ long long sc[128];
    const int tid = threadIdx.x;
    double a = 0.0;
    long long ch = 0;
    for (int i = tid; i < NPART; i += 128) a += g_pacc[i];
    for (int i = tid; i < BATCH; i += 128) ch += (long long)g_len[i];
    sa[tid] = a; sc[tid] = ch;
    __syncthreads();
    for (int o = 64; o; o >>= 1) {
        if (tid < o) { sa[tid] += sa[tid + o]; sc[tid] += sc[tid + o]; }
        __syncthreads();
    }
    if (tid == 0) out[0] = (float)(sa[0] / (double)sc[0]);
}

extern "C" void kernel_launch(void* const* d_in, const int* in_sizes, int n_in,
                              void* d_out, int out_size)
{
    const float* bert  = (const float*)d_in[0];
    const int*   mask  = (const int*)d_in[1];
    const int*   tags  = (const int*)d_in[2];
    const float* trans = (const float*)d_in[3];
    float* out = (float*)d_out;

    cudaFuncSetAttribute(crf_scan, cudaFuncAttributeMaxDynamicSharedMemorySize, DSMEM);

    crf_len_hist<<<BATCH / 4, 128>>>(mask);
    crf_prefix<<<1, 512>>>();
    crf_scatter<<<BATCH / 128, 128>>>();
    dim3 grid(32, NCHUNK);
    crf_scan<<<grid, 128, DSMEM>>>(bert, tags, trans);
    crf_fin<<<1, 128>>>(out);
}